// round 13
// baseline (speedup 1.0000x reference)
#include <cuda_runtime.h>
#include <stdint.h>

// Problem constants
#define NT    256      // threads per CTA (4 groups x 64 channels)
#define NBSUB 2        // b-values per thread
#define NB    8        // b-values per CTA
#define DIM   40
#define NPAIR 820      // DIM*(DIM+1)/2 unique symmetric pairs
#define NROWS 860      // pairs + 40 U1 rows
#define XROWB 2048     // x row stride in bytes (256 threads * 8B)

// Split coefficient table, ROW-MAJOR TRIANGULAR order (i outer, j from i):
//  part A (constant): per row, coeffs m0..m7   (8 floats, 32B)
//  part B (shared):   per row, coeffs m8..m12 + 3 pad (8 floats, 32B)
__device__ float g_tabA[NROWS * 8];
__device__ float g_tabB[NROWS * 8];
__constant__ float c_tabA[NROWS * 8];   // 27.5 KB of 64 KB budget

__global__ void prep_kernel(const float* __restrict__ U2_0,
                            const float* __restrict__ U1_0,
                            const float* __restrict__ U2_1,
                            const float* __restrict__ U1_1,
                            const float* __restrict__ U2_2,
                            const float* __restrict__ U1_2) {
    int idx = blockIdx.x * blockDim.x + threadIdx.x;
    if (idx >= NROWS) return;
    float row[16];
#pragma unroll
    for (int k = 0; k < 16; k++) row[k] = 0.0f;

    if (idx < NPAIR) {
        // invert p -> (i, j) for row-major triangular order (i outer, j from i)
        int rem = idx;
        int i = 0;
        while (rem >= DIM - i) { rem -= DIM - i; i++; }
        int j = i + rem;
        const float* U2b[3] = {U2_0, U2_1, U2_2};
#pragma unroll
        for (int m = 0; m < 13; m++) {
            int l  = (m == 0) ? 0 : ((m < 4) ? 1 : 2);
            int mm = (m == 0) ? 0 : ((m < 4) ? (m - 1) : (m - 4));
            const float* U = U2b[l];
            float v = U[(mm * DIM + i) * DIM + j];
            if (i != j) v += U[(mm * DIM + j) * DIM + i];
            row[m] = v;
        }
    } else {
        int i = idx - NPAIR;
        const float* U1b[3] = {U1_0, U1_1, U1_2};
#pragma unroll
        for (int m = 0; m < 13; m++) {
            int l  = (m == 0) ? 0 : ((m < 4) ? 1 : 2);
            int mm = (m == 0) ? 0 : ((m < 4) ? (m - 1) : (m - 4));
            row[m] = U1b[l][mm * DIM + i];
        }
    }
#pragma unroll
    for (int k = 0; k < 8; k++) g_tabA[idx * 8 + k] = row[k];      // m0..m7
#pragma unroll
    for (int k = 0; k < 5; k++) g_tabB[idx * 8 + k] = row[8 + k];  // m8..m12
#pragma unroll
    for (int k = 5; k < 8; k++) g_tabB[idx * 8 + k] = 0.0f;
}

// ---- packed f32x2 helpers ----
__device__ __forceinline__ void fma2(unsigned long long& acc,
                                     unsigned long long u,
                                     unsigned long long y) {
    asm("fma.rn.f32x2 %0, %1, %2, %0;" : "+l"(acc) : "l"(u), "l"(y));
}
__device__ __forceinline__ unsigned long long dup2(float y) {
    unsigned long long r;
    asm("mov.b64 %0, {%1, %1};" : "=l"(r) : "f"(y));
    return r;
}
__device__ __forceinline__ float2 unpk2(unsigned long long v) {
    float2 r;
    asm("mov.b64 {%0, %1}, %2;" : "=f"(r.x), "=f"(r.y) : "l"(v));
    return r;
}

// SMEM layout (floats) — 110 KB per CTA => 2 CTAs/SM:
//   [0,     20480)  xS: x[40][256 threads][2 b]
//                   reused after phases: Wlin (12288) + basis[8][64][16] (8192)
//   [20480, 27360)  tabB: 860 rows x 8 floats (m8..m12)
#define TABB_OFF 20480
#define SMEM_FLOATS 27360
#define SMEM_BYTES  (SMEM_FLOATS * 4)
#define BSTRIDE 16     // basis row stride in floats

__global__ __launch_bounds__(NT, 2)
void main_kernel(const float* __restrict__ f0,  const float* __restrict__ f1,
                 const float* __restrict__ f2,  const float* __restrict__ f3,
                 const float* __restrict__ attrs,
                 const float* __restrict__ W1_0, const float* __restrict__ W2_0,
                 const float* __restrict__ Wl0,  const float* __restrict__ sc0,
                 const float* __restrict__ W1_1, const float* __restrict__ W2_1,
                 const float* __restrict__ Wl1,  const float* __restrict__ sc1,
                 const float* __restrict__ W1_2, const float* __restrict__ W2_2,
                 const float* __restrict__ Wl2,  const float* __restrict__ sc2,
                 float* __restrict__ out, int B) {
    extern __shared__ float S[];
    float* xS   = S;            // 20480 floats
    float* tbS  = S + TABB_OFF; // 6880 floats

    const int tid = threadIdx.x;
    const int g   = tid >> 6;        // b-group 0..3
    const int c   = tid & 63;        // channel
    const int b0  = blockIdx.x * NB + g * NBSUB;

    // cooperative copy of table part B into smem (860*8/4 = 1720 float4)
    {
        const float4* gt4 = (const float4*)g_tabB;
        float4* tp4 = (float4*)tbS;
#pragma unroll
        for (int k = 0; k < 7; k++) {
            int idx = k * NT + tid;
            if (idx < NROWS * 2) tp4[idx] = gt4[idx];
        }
    }

    // gather x for 2 b's: xS[i*512 + tid*2 + s]
#pragma unroll
    for (int s = 0; s < NBSUB; s++) {
        int bb = b0 + s; if (bb >= B) bb = B - 1;
        const int base = bb * 64 + c;
        xS[tid * 2 + s] = f0[base];
#pragma unroll
        for (int k = 0; k < 3; k++)
            xS[(1 + k) * 512 + tid * 2 + s]  = f1[base * 3 + k];
#pragma unroll
        for (int k = 0; k < 9; k++)
            xS[(4 + k) * 512 + tid * 2 + s]  = f2[base * 9 + k];
#pragma unroll
        for (int k = 0; k < 27; k++)
            xS[(13 + k) * 512 + tid * 2 + s] = f3[base * 27 + k];
    }
    __syncthreads();

    const char* xtb = (const char*)xS + tid * 8;

    // ---- phase A: a2[s][m] = sum_{i<=j} u[p][m] * x_i[s] * x_j[s] ----
    // m0..m7 from CONSTANT port (2x LDC.128), m8..m12 from smem broadcast
    // (LDS.128 + LDS.64) — load split across both read ports so the fma
    // pipe is the only saturated resource.
    unsigned long long a2[NBSUB][7];
#pragma unroll
    for (int s = 0; s < NBSUB; s++)
#pragma unroll
        for (int k = 0; k < 7; k++) a2[s][k] = 0ull;

    {
        const ulonglong2* tc = (const ulonglong2*)c_tabA;
        const ulonglong2* ts = (const ulonglong2*)tbS;
        for (int i = 0; i < DIM; i++) {
            const float2 xi = *(const float2*)(xtb + i * XROWB);
            const char* xjp = xtb + i * XROWB;
#pragma unroll 2
            for (int j = i; j < DIM; j++) {
                ulonglong2 q0 = tc[0];
                ulonglong2 q1 = tc[1];
                tc += 2;
                ulonglong2 q2 = ts[0];
                unsigned long long q3 = ((const unsigned long long*)ts)[2];
                ts += 2;
                float2 xj = *(const float2*)xjp;
                xjp += XROWB;
                unsigned long long y0 = dup2(xi.x * xj.x);
                unsigned long long y1 = dup2(xi.y * xj.y);
                fma2(a2[0][0], q0.x, y0); fma2(a2[1][0], q0.x, y1);
                fma2(a2[0][1], q0.y, y0); fma2(a2[1][1], q0.y, y1);
                fma2(a2[0][2], q1.x, y0); fma2(a2[1][2], q1.x, y1);
                fma2(a2[0][3], q1.y, y0); fma2(a2[1][3], q1.y, y1);
                fma2(a2[0][4], q2.x, y0); fma2(a2[1][4], q2.x, y1);
                fma2(a2[0][5], q2.y, y0); fma2(a2[1][5], q2.y, y1);
                fma2(a2[0][6], q3,   y0); fma2(a2[1][6], q3,   y1);
            }
        }
    }

    // ---- phase B: a1[s][m] = U1[m,:] . x[s] ----
    unsigned long long a1[NBSUB][7];
#pragma unroll
    for (int s = 0; s < NBSUB; s++)
#pragma unroll
        for (int k = 0; k < 7; k++) a1[s][k] = 0ull;

    {
        const ulonglong2* tc = (const ulonglong2*)c_tabA + NPAIR * 2;
        const ulonglong2* ts = (const ulonglong2*)tbS + NPAIR * 2;
#pragma unroll 2
        for (int i = 0; i < DIM; i++, tc += 2, ts += 2) {
            ulonglong2 q0 = tc[0];
            ulonglong2 q1 = tc[1];
            ulonglong2 q2 = ts[0];
            unsigned long long q3 = ((const unsigned long long*)ts)[2];
            float2 xi = *(const float2*)(xtb + i * XROWB);
            unsigned long long y0 = dup2(xi.x);
            unsigned long long y1 = dup2(xi.y);
            fma2(a1[0][0], q0.x, y0); fma2(a1[1][0], q0.x, y1);
            fma2(a1[0][1], q0.y, y0); fma2(a1[1][1], q0.y, y1);
            fma2(a1[0][2], q1.x, y0); fma2(a1[1][2], q1.x, y1);
            fma2(a1[0][3], q1.y, y0); fma2(a1[1][3], q1.y, y1);
            fma2(a1[0][4], q2.x, y0); fma2(a1[1][4], q2.x, y1);
            fma2(a1[0][5], q2.y, y0); fma2(a1[1][5], q2.y, y1);
            fma2(a1[0][6], q3,   y0); fma2(a1[1][6], q3,   y1);
        }
    }

    __syncthreads();   // everyone done reading xS before we overwrite it

    // reuse xS region: Wlin cache + basis16
    float* wlS  = xS;               // 12288 floats
    float* basS = xS + 12288;       // 8192 floats

    // Wlin cache: wlS[l*4096 + cc*64 + o]
    {
        const float4* a0p = (const float4*)Wl0;
        const float4* a1p = (const float4*)Wl1;
        const float4* a2p = (const float4*)Wl2;
        float4* w4 = (float4*)wlS;
#pragma unroll
        for (int k = 0; k < 4; k++) {
            int idx = k * NT + tid;
            w4[idx]        = a0p[idx];
            w4[1024 + idx] = a1p[idx];
            w4[2048 + idx] = a2p[idx];
        }
    }

    // fold: basis = a1*w1 + a2*w2 (element-aware weights computed here)
    const int LSEL[14] = {0, 1, 1, 1, 2, 2, 2, 2, 2, 2, 2, 2, 2, 0};
#pragma unroll
    for (int s = 0; s < NBSUB; s++) {
        int bb = b0 + s; if (bb >= B) bb = B - 1;
        float w10 = 0.f, w11 = 0.f, w12 = 0.f;
        float w20 = 0.f, w21 = 0.f, w22 = 0.f;
#pragma unroll
        for (int e = 0; e < 10; e++) {
            float a = __ldg(&attrs[bb * 10 + e]);
            w10 += a * __ldg(&W1_0[e * 64 + c]);
            w20 += a * __ldg(&W2_0[e * 64 + c]);
            w11 += a * __ldg(&W1_1[e * 64 + c]);
            w21 += a * __ldg(&W2_1[e * 64 + c]);
            w12 += a * __ldg(&W1_2[e * 64 + c]);
            w22 += a * __ldg(&W2_2[e * 64 + c]);
        }
        float w1v[3] = {w10, w11, w12};
        float w2v[3] = {w20, w21, w22};
        float* bs = basS + ((g * NBSUB + s) * 64 + c) * BSTRIDE;
#pragma unroll
        for (int k = 0; k < 7; k++) {
            float2 v2 = unpk2(a2[s][k]);
            float2 v1 = unpk2(a1[s][k]);
            int m0 = 2 * k, m1 = 2 * k + 1;
            bs[m0] = v1.x * w1v[LSEL[m0]] + v2.x * w2v[LSEL[m0]];
            if (m1 < 13)
                bs[m1] = v1.y * w1v[LSEL[m1]] + v2.y * w2v[LSEL[m1]];
        }
    }
    __syncthreads();

    // ---- self-interaction: r[s][m] = sum_cc basis[b_s][cc][m] * Wlin_l[cc][c] ----
    float r[NBSUB][13];
#pragma unroll
    for (int s = 0; s < NBSUB; s++)
#pragma unroll
        for (int m = 0; m < 13; m++) r[s][m] = 0.0f;

#pragma unroll 2
    for (int cc = 0; cc < 64; cc++) {
        float wv0 = wlS[cc * 64 + c];
        float wv1 = wlS[4096 + cc * 64 + c];
        float wv2 = wlS[8192 + cc * 64 + c];
#pragma unroll
        for (int s = 0; s < NBSUB; s++) {
            const float* br = basS + ((g * NBSUB + s) * 64 + cc) * BSTRIDE;
            float4 q0 = *(const float4*)(br);
            float4 q1 = *(const float4*)(br + 4);
            float4 q2 = *(const float4*)(br + 8);
            float b12 = br[12];
            r[s][0]  += q0.x * wv0;
            r[s][1]  += q0.y * wv1;
            r[s][2]  += q0.z * wv1;
            r[s][3]  += q0.w * wv1;
            r[s][4]  += q1.x * wv2;
            r[s][5]  += q1.y * wv2;
            r[s][6]  += q1.z * wv2;
            r[s][7]  += q1.w * wv2;
            r[s][8]  += q2.x * wv2;
            r[s][9]  += q2.y * wv2;
            r[s][10] += q2.z * wv2;
            r[s][11] += q2.w * wv2;
            r[s][12] += b12  * wv2;
        }
    }

    // ---- outputs: concat [out0 (B,C)] [out1 (B,C,3)] [out2 (B,C,9)] ----
    float* o0 = out;
    float* o1 = out + (size_t)B * 64;
    float* o2 = out + (size_t)B * 64 * 4;
#pragma unroll
    for (int s = 0; s < NBSUB; s++) {
        int bb = b0 + s;
        if (bb >= B) break;
        const int bo = bb * 64 + c;
        o0[bo] = r[s][0] + __ldg(&sc0[bo]);
#pragma unroll
        for (int k = 0; k < 3; k++)
            o1[bo * 3 + k] = r[s][1 + k] + __ldg(&sc1[bo * 3 + k]);
#pragma unroll
        for (int k = 0; k < 9; k++)
            o2[bo * 9 + k] = r[s][4 + k] + __ldg(&sc2[bo * 9 + k]);
    }
}

extern "C" void kernel_launch(void* const* d_in, const int* in_sizes, int n_in,
                              void* d_out, int out_size) {
    const float* f0    = (const float*)d_in[0];
    const float* f1    = (const float*)d_in[1];
    const float* f2    = (const float*)d_in[2];
    const float* f3    = (const float*)d_in[3];
    const float* attrs = (const float*)d_in[4];
    const float* U2_0  = (const float*)d_in[5];
    const float* U1_0  = (const float*)d_in[6];
    const float* W1_0  = (const float*)d_in[7];
    const float* W2_0  = (const float*)d_in[8];
    const float* Wl0   = (const float*)d_in[9];
    const float* sc0   = (const float*)d_in[10];
    const float* U2_1  = (const float*)d_in[11];
    const float* U1_1  = (const float*)d_in[12];
    const float* W1_1  = (const float*)d_in[13];
    const float* W2_1  = (const float*)d_in[14];
    const float* Wl1   = (const float*)d_in[15];
    const float* sc1   = (const float*)d_in[16];
    const float* U2_2  = (const float*)d_in[17];
    const float* U1_2  = (const float*)d_in[18];
    const float* W1_2  = (const float*)d_in[19];
    const float* W2_2  = (const float*)d_in[20];
    const float* Wl2   = (const float*)d_in[21];
    const float* sc2   = (const float*)d_in[22];

    const int B = in_sizes[0] / 64;

    cudaFuncSetAttribute(main_kernel,
                         cudaFuncAttributeMaxDynamicSharedMemorySize, SMEM_BYTES);

    prep_kernel<<<(NROWS + 255) / 256, 256>>>(U2_0, U1_0, U2_1, U1_1, U2_2, U1_2);

    // copy staged table part A into constant memory (graph-capturable D2D)
    void* src = nullptr;
    void* dst = nullptr;
    cudaGetSymbolAddress(&src, g_tabA);
    cudaGetSymbolAddress(&dst, c_tabA);
    cudaMemcpyAsync(dst, src, NROWS * 8 * sizeof(float),
                    cudaMemcpyDeviceToDevice, 0);

    const int grid = (B + NB - 1) / NB;
    main_kernel<<<grid, NT, SMEM_BYTES>>>(f0, f1, f2, f3, attrs,
                                          W1_0, W2_0, Wl0, sc0,
                                          W1_1, W2_1, Wl1, sc1,
                                          W1_2, W2_2, Wl2, sc2,
                                          (float*)d_out, B);
}

// round 14
// speedup vs baseline: 1.1510x; 1.1510x over previous
#include <cuda_runtime.h>
#include <stdint.h>

// Problem constants
#define NT    256      // threads per CTA (4 groups x 64 channels)
#define NBSUB 2        // b-values per thread
#define NB    8        // b-values per CTA
#define DIM   40
#define NPAIR 820      // DIM*(DIM+1)/2 unique symmetric pairs
#define NROWS 860      // pairs + 40 U1 rows
#define TS    16       // table row stride (floats)
#define XROWB 2048     // x row stride in bytes (256 threads * 8B)

// Staging table in global, then copied into constant memory.
__device__ float g_table[NROWS * TS];
__constant__ float c_table[NROWS * TS];   // 55 KB of 64 KB budget

__global__ void prep_kernel(const float* __restrict__ U2_0,
                            const float* __restrict__ U1_0,
                            const float* __restrict__ U2_1,
                            const float* __restrict__ U1_1,
                            const float* __restrict__ U2_2,
                            const float* __restrict__ U1_2) {
    int idx = blockIdx.x * blockDim.x + threadIdx.x;
    if (idx >= NROWS) return;
    float row[TS];
#pragma unroll
    for (int k = 0; k < TS; k++) row[k] = 0.0f;

    if (idx < NPAIR) {
        // invert p -> (i, j) for row-major triangular order (i outer, j from i)
        int rem = idx;
        int i = 0;
        while (rem >= DIM - i) { rem -= DIM - i; i++; }
        int j = i + rem;
        const float* U2b[3] = {U2_0, U2_1, U2_2};
#pragma unroll
        for (int m = 0; m < 13; m++) {
            int l  = (m == 0) ? 0 : ((m < 4) ? 1 : 2);
            int mm = (m == 0) ? 0 : ((m < 4) ? (m - 1) : (m - 4));
            const float* U = U2b[l];
            float v = U[(mm * DIM + i) * DIM + j];
            if (i != j) v += U[(mm * DIM + j) * DIM + i];
            row[m] = v;
        }
    } else {
        int i = idx - NPAIR;
        const float* U1b[3] = {U1_0, U1_1, U1_2};
#pragma unroll
        for (int m = 0; m < 13; m++) {
            int l  = (m == 0) ? 0 : ((m < 4) ? 1 : 2);
            int mm = (m == 0) ? 0 : ((m < 4) ? (m - 1) : (m - 4));
            row[m] = U1b[l][mm * DIM + i];
        }
    }
#pragma unroll
    for (int k = 0; k < TS; k++) g_table[idx * TS + k] = row[k];
}

// ---- packed f32x2 helpers ----
__device__ __forceinline__ void fma2(unsigned long long& acc,
                                     unsigned long long u,
                                     unsigned long long y) {
    asm("fma.rn.f32x2 %0, %1, %2, %0;" : "+l"(acc) : "l"(u), "l"(y));
}
__device__ __forceinline__ unsigned long long dup2(float y) {
    unsigned long long r;
    asm("mov.b64 %0, {%1, %1};" : "=l"(r) : "f"(y));
    return r;
}
__device__ __forceinline__ float2 unpk2(unsigned long long v) {
    float2 r;
    asm("mov.b64 {%0, %1}, %2;" : "=f"(r.x), "=f"(r.y) : "l"(v));
    return r;
}

// SMEM layout (floats) — 80 KB per CTA => 2 CTAs/SM:
//   [0, 20480)  xS: x[40][256 threads][2 b]
//               reused after phases: Wlin (12288) + basis[8][64][16] (8192)
#define SMEM_FLOATS 20480
#define SMEM_BYTES  (SMEM_FLOATS * 4)
#define BSTRIDE 16     // basis row stride in floats

__global__ __launch_bounds__(NT, 2)
void main_kernel(const float* __restrict__ f0,  const float* __restrict__ f1,
                 const float* __restrict__ f2,  const float* __restrict__ f3,
                 const float* __restrict__ attrs,
                 const float* __restrict__ W1_0, const float* __restrict__ W2_0,
                 const float* __restrict__ Wl0,  const float* __restrict__ sc0,
                 const float* __restrict__ W1_1, const float* __restrict__ W2_1,
                 const float* __restrict__ Wl1,  const float* __restrict__ sc1,
                 const float* __restrict__ W1_2, const float* __restrict__ W2_2,
                 const float* __restrict__ Wl2,  const float* __restrict__ sc2,
                 float* __restrict__ out, int B) {
    extern __shared__ float S[];
    float* xS = S;   // 20480 floats

    const int tid = threadIdx.x;
    const int g   = tid >> 6;        // b-group 0..3
    const int c   = tid & 63;        // channel
    const int b0  = blockIdx.x * NB + g * NBSUB;

    // gather x for 2 b's: xS[i*512 + tid*2 + s]
#pragma unroll
    for (int s = 0; s < NBSUB; s++) {
        int bb = b0 + s; if (bb >= B) bb = B - 1;
        const int base = bb * 64 + c;
        xS[tid * 2 + s] = f0[base];
#pragma unroll
        for (int k = 0; k < 3; k++)
            xS[(1 + k) * 512 + tid * 2 + s]  = f1[base * 3 + k];
#pragma unroll
        for (int k = 0; k < 9; k++)
            xS[(4 + k) * 512 + tid * 2 + s]  = f2[base * 9 + k];
#pragma unroll
        for (int k = 0; k < 27; k++)
            xS[(13 + k) * 512 + tid * 2 + s] = f3[base * 27 + k];
    }
    __syncthreads();

    const char* xtb = (const char*)xS + tid * 8;

    // ---- phase A: a2[s][m] = sum_{i<=j} u[p][m] * x_i[s] * x_j[s] ----
    // Table rows from CONSTANT memory as 64/128-bit words; unroll 4 for
    // deep LDC lookahead (LDC latency ~30cyc must hide under FFMA2 bursts).
    unsigned long long a2[NBSUB][7];
#pragma unroll
    for (int s = 0; s < NBSUB; s++)
#pragma unroll
        for (int k = 0; k < 7; k++) a2[s][k] = 0ull;

    {
        const ulonglong2* trow = (const ulonglong2*)c_table;
        for (int i = 0; i < DIM; i++) {
            const float2 xi = *(const float2*)(xtb + i * XROWB);
            const char* xjp = xtb + i * XROWB;
#pragma unroll 4
            for (int j = i; j < DIM; j++) {
                ulonglong2 q0 = trow[0];
                ulonglong2 q1 = trow[1];
                ulonglong2 q2 = trow[2];
                unsigned long long q3 = ((const unsigned long long*)trow)[6];
                trow += 4;
                float2 xj = *(const float2*)xjp;
                xjp += XROWB;
                unsigned long long y0 = dup2(xi.x * xj.x);
                unsigned long long y1 = dup2(xi.y * xj.y);
                fma2(a2[0][0], q0.x, y0); fma2(a2[1][0], q0.x, y1);
                fma2(a2[0][1], q0.y, y0); fma2(a2[1][1], q0.y, y1);
                fma2(a2[0][2], q1.x, y0); fma2(a2[1][2], q1.x, y1);
                fma2(a2[0][3], q1.y, y0); fma2(a2[1][3], q1.y, y1);
                fma2(a2[0][4], q2.x, y0); fma2(a2[1][4], q2.x, y1);
                fma2(a2[0][5], q2.y, y0); fma2(a2[1][5], q2.y, y1);
                fma2(a2[0][6], q3,   y0); fma2(a2[1][6], q3,   y1);
            }
        }
    }

    // ---- phase B: a1[s][m] = U1[m,:] . x[s] ----
    unsigned long long a1[NBSUB][7];
#pragma unroll
    for (int s = 0; s < NBSUB; s++)
#pragma unroll
        for (int k = 0; k < 7; k++) a1[s][k] = 0ull;

    {
        const ulonglong2* trow = (const ulonglong2*)c_table + NPAIR * 4;
#pragma unroll 4
        for (int i = 0; i < DIM; i++, trow += 4) {
            ulonglong2 q0 = trow[0];
            ulonglong2 q1 = trow[1];
            ulonglong2 q2 = trow[2];
            unsigned long long q3 = ((const unsigned long long*)trow)[6];
            float2 xi = *(const float2*)(xtb + i * XROWB);
            unsigned long long y0 = dup2(xi.x);
            unsigned long long y1 = dup2(xi.y);
            fma2(a1[0][0], q0.x, y0); fma2(a1[1][0], q0.x, y1);
            fma2(a1[0][1], q0.y, y0); fma2(a1[1][1], q0.y, y1);
            fma2(a1[0][2], q1.x, y0); fma2(a1[1][2], q1.x, y1);
            fma2(a1[0][3], q1.y, y0); fma2(a1[1][3], q1.y, y1);
            fma2(a1[0][4], q2.x, y0); fma2(a1[1][4], q2.x, y1);
            fma2(a1[0][5], q2.y, y0); fma2(a1[1][5], q2.y, y1);
            fma2(a1[0][6], q3,   y0); fma2(a1[1][6], q3,   y1);
        }
    }

    __syncthreads();   // everyone done reading xS before we overwrite it

    // reuse xS region: Wlin cache + basis16
    float* wlS  = xS;               // 12288 floats
    float* basS = xS + 12288;       // 8192 floats

    // Wlin cache: wlS[l*4096 + cc*64 + o]
    {
        const float4* a0p = (const float4*)Wl0;
        const float4* a1p = (const float4*)Wl1;
        const float4* a2p = (const float4*)Wl2;
        float4* w4 = (float4*)wlS;
#pragma unroll
        for (int k = 0; k < 4; k++) {
            int idx = k * NT + tid;
            w4[idx]        = a0p[idx];
            w4[1024 + idx] = a1p[idx];
            w4[2048 + idx] = a2p[idx];
        }
    }

    // fold: basis = a1*w1 + a2*w2 (element-aware weights computed here)
    const int LSEL[14] = {0, 1, 1, 1, 2, 2, 2, 2, 2, 2, 2, 2, 2, 0};
#pragma unroll
    for (int s = 0; s < NBSUB; s++) {
        int bb = b0 + s; if (bb >= B) bb = B - 1;
        float w10 = 0.f, w11 = 0.f, w12 = 0.f;
        float w20 = 0.f, w21 = 0.f, w22 = 0.f;
#pragma unroll
        for (int e = 0; e < 10; e++) {
            float a = __ldg(&attrs[bb * 10 + e]);
            w10 += a * __ldg(&W1_0[e * 64 + c]);
            w20 += a * __ldg(&W2_0[e * 64 + c]);
            w11 += a * __ldg(&W1_1[e * 64 + c]);
            w21 += a * __ldg(&W2_1[e * 64 + c]);
            w12 += a * __ldg(&W1_2[e * 64 + c]);
            w22 += a * __ldg(&W2_2[e * 64 + c]);
        }
        float w1v[3] = {w10, w11, w12};
        float w2v[3] = {w20, w21, w22};
        float* bs = basS + ((g * NBSUB + s) * 64 + c) * BSTRIDE;
#pragma unroll
        for (int k = 0; k < 7; k++) {
            float2 v2 = unpk2(a2[s][k]);
            float2 v1 = unpk2(a1[s][k]);
            int m0 = 2 * k, m1 = 2 * k + 1;
            bs[m0] = v1.x * w1v[LSEL[m0]] + v2.x * w2v[LSEL[m0]];
            if (m1 < 13)
                bs[m1] = v1.y * w1v[LSEL[m1]] + v2.y * w2v[LSEL[m1]];
        }
    }
    __syncthreads();

    // ---- self-interaction: r[s][m] = sum_cc basis[b_s][cc][m] * Wlin_l[cc][c] ----
    float r[NBSUB][13];
#pragma unroll
    for (int s = 0; s < NBSUB; s++)
#pragma unroll
        for (int m = 0; m < 13; m++) r[s][m] = 0.0f;

#pragma unroll 2
    for (int cc = 0; cc < 64; cc++) {
        float wv0 = wlS[cc * 64 + c];
        float wv1 = wlS[4096 + cc * 64 + c];
        float wv2 = wlS[8192 + cc * 64 + c];
#pragma unroll
        for (int s = 0; s < NBSUB; s++) {
            const float* br = basS + ((g * NBSUB + s) * 64 + cc) * BSTRIDE;
            float4 q0 = *(const float4*)(br);
            float4 q1 = *(const float4*)(br + 4);
            float4 q2 = *(const float4*)(br + 8);
            float b12 = br[12];
            r[s][0]  += q0.x * wv0;
            r[s][1]  += q0.y * wv1;
            r[s][2]  += q0.z * wv1;
            r[s][3]  += q0.w * wv1;
            r[s][4]  += q1.x * wv2;
            r[s][5]  += q1.y * wv2;
            r[s][6]  += q1.z * wv2;
            r[s][7]  += q1.w * wv2;
            r[s][8]  += q2.x * wv2;
            r[s][9]  += q2.y * wv2;
            r[s][10] += q2.z * wv2;
            r[s][11] += q2.w * wv2;
            r[s][12] += b12  * wv2;
        }
    }

    // ---- outputs: concat [out0 (B,C)] [out1 (B,C,3)] [out2 (B,C,9)] ----
    float* o0 = out;
    float* o1 = out + (size_t)B * 64;
    float* o2 = out + (size_t)B * 64 * 4;
#pragma unroll
    for (int s = 0; s < NBSUB; s++) {
        int bb = b0 + s;
        if (bb >= B) break;
        const int bo = bb * 64 + c;
        o0[bo] = r[s][0] + __ldg(&sc0[bo]);
#pragma unroll
        for (int k = 0; k < 3; k++)
            o1[bo * 3 + k] = r[s][1 + k] + __ldg(&sc1[bo * 3 + k]);
#pragma unroll
        for (int k = 0; k < 9; k++)
            o2[bo * 9 + k] = r[s][4 + k] + __ldg(&sc2[bo * 9 + k]);
    }
}

extern "C" void kernel_launch(void* const* d_in, const int* in_sizes, int n_in,
                              void* d_out, int out_size) {
    const float* f0    = (const float*)d_in[0];
    const float* f1    = (const float*)d_in[1];
    const float* f2    = (const float*)d_in[2];
    const float* f3    = (const float*)d_in[3];
    const float* attrs = (const float*)d_in[4];
    const float* U2_0  = (const float*)d_in[5];
    const float* U1_0  = (const float*)d_in[6];
    const float* W1_0  = (const float*)d_in[7];
    const float* W2_0  = (const float*)d_in[8];
    const float* Wl0   = (const float*)d_in[9];
    const float* sc0   = (const float*)d_in[10];
    const float* U2_1  = (const float*)d_in[11];
    const float* U1_1  = (const float*)d_in[12];
    const float* W1_1  = (const float*)d_in[13];
    const float* W2_1  = (const float*)d_in[14];
    const float* Wl1   = (const float*)d_in[15];
    const float* sc1   = (const float*)d_in[16];
    const float* U2_2  = (const float*)d_in[17];
    const float* U1_2  = (const float*)d_in[18];
    const float* W1_2  = (const float*)d_in[19];
    const float* W2_2  = (const float*)d_in[20];
    const float* Wl2   = (const float*)d_in[21];
    const float* sc2   = (const float*)d_in[22];

    const int B = in_sizes[0] / 64;

    cudaFuncSetAttribute(main_kernel,
                         cudaFuncAttributeMaxDynamicSharedMemorySize, SMEM_BYTES);

    prep_kernel<<<(NROWS + 255) / 256, 256>>>(U2_0, U1_0, U2_1, U1_1, U2_2, U1_2);

    // copy staged table into constant memory (graph-capturable D2D memcpy)
    void* src = nullptr;
    void* dst = nullptr;
    cudaGetSymbolAddress(&src, g_table);
    cudaGetSymbolAddress(&dst, c_table);
    cudaMemcpyAsync(dst, src, NROWS * TS * sizeof(float),
                    cudaMemcpyDeviceToDevice, 0);

    const int grid = (B + NB - 1) / NB;
    main_kernel<<<grid, NT, SMEM_BYTES>>>(f0, f1, f2, f3, attrs,
                                          W1_0, W2_0, Wl0, sc0,
                                          W1_1, W2_1, Wl1, sc1,
                                          W1_2, W2_2, Wl2, sc2,
                                          (float*)d_out, B);
}

// round 15
// speedup vs baseline: 1.2375x; 1.0751x over previous
#include <cuda_runtime.h>
#include <stdint.h>

// ---- problem constants ----
#define NT     256
#define NB     8          // b per CTA
#define ROWS   512        // NB * 64 rows per CTA
#define DIM    40
#define NPAIR  820
#define KP     832        // padded K = 104 ksteps of 8
#define NSTEP  (KP / 8)
#define XST    520        // xst row stride (floats): bank = (8i + r) % 32 -> conflict-free frags
#define BST    24         // Bs row stride (floats): 24q%32 = {0,24,16,8} -> conflict-free B frags
#define BAS    18         // basis row stride (floats): even (float2 ok), 2-way max conflicts

// ---- staged tables (filled by prep_kernel) ----
__device__ float g_B[KP * 16];     // B[k][n]: tf32-rounded folded U2 coeffs; zero-padded
__device__ uint2 g_idx[KP];        // per k: byte offsets (i*XST*4, j*XST*4) into xst
__device__ float g_u1[DIM * 16];   // U1 rows, old 16-float layout (13 coeffs + pad)
__constant__ float c_u1t[DIM * 16];

__global__ void prep_kernel(const float* __restrict__ U2_0,
                            const float* __restrict__ U1_0,
                            const float* __restrict__ U2_1,
                            const float* __restrict__ U1_1,
                            const float* __restrict__ U2_2,
                            const float* __restrict__ U1_2) {
    int idx = blockIdx.x * blockDim.x + threadIdx.x;
    if (idx >= KP + DIM) return;

    if (idx < KP) {
        float row[16];
#pragma unroll
        for (int k = 0; k < 16; k++) row[k] = 0.0f;
        int i = 0, j = 0;
        if (idx < NPAIR) {
            int rem = idx;
            while (rem >= DIM - i) { rem -= DIM - i; i++; }
            j = i + rem;
            const float* U2b[3] = {U2_0, U2_1, U2_2};
#pragma unroll
            for (int m = 0; m < 13; m++) {
                int l  = (m == 0) ? 0 : ((m < 4) ? 1 : 2);
                int mm = (m == 0) ? 0 : ((m < 4) ? (m - 1) : (m - 4));
                const float* U = U2b[l];
                float v = U[(mm * DIM + i) * DIM + j];
                if (i != j) v += U[(mm * DIM + j) * DIM + i];
                // round to tf32 (RNA) so the HW truncation inside HMMA is exact
                unsigned int o;
                asm("cvt.rna.tf32.f32 %0, %1;" : "=r"(o) : "f"(v));
                row[m] = __uint_as_float(o);
            }
        }
#pragma unroll
        for (int k = 0; k < 16; k++) g_B[idx * 16 + k] = row[k];
        g_idx[idx] = make_uint2((unsigned)(i * XST * 4), (unsigned)(j * XST * 4));
    } else {
        int i = idx - KP;
        float row[16];
#pragma unroll
        for (int k = 0; k < 16; k++) row[k] = 0.0f;
        const float* U1b[3] = {U1_0, U1_1, U1_2};
#pragma unroll
        for (int m = 0; m < 13; m++) {
            int l  = (m == 0) ? 0 : ((m < 4) ? 1 : 2);
            int mm = (m == 0) ? 0 : ((m < 4) ? (m - 1) : (m - 4));
            row[m] = U1b[l][mm * DIM + i];
        }
#pragma unroll
        for (int k = 0; k < 16; k++) g_u1[i * 16 + k] = row[k];
    }
}

// ---- packed f32x2 helpers (for the a1 phase) ----
__device__ __forceinline__ void fma2(unsigned long long& acc,
                                     unsigned long long u,
                                     unsigned long long y) {
    asm("fma.rn.f32x2 %0, %1, %2, %0;" : "+l"(acc) : "l"(u), "l"(y));
}
__device__ __forceinline__ unsigned long long dup2(float y) {
    unsigned long long r;
    asm("mov.b64 %0, {%1, %1};" : "=l"(r) : "f"(y));
    return r;
}
__device__ __forceinline__ float2 unpk2(unsigned long long v) {
    float2 r;
    asm("mov.b64 {%0, %1}, %2;" : "=f"(r.x), "=f"(r.y) : "l"(v));
    return r;
}

// ---- tf32 mma.sync m16n8k8 ----
__device__ __forceinline__ void mma_tf32(float* c,
                                         float a0, float a1, float a2, float a3,
                                         float b0, float b1) {
    asm volatile(
        "mma.sync.aligned.m16n8k8.row.col.f32.tf32.tf32.f32 "
        "{%0,%1,%2,%3},{%4,%5,%6,%7},{%8,%9},{%0,%1,%2,%3};"
        : "+f"(c[0]), "+f"(c[1]), "+f"(c[2]), "+f"(c[3])
        : "r"(__float_as_uint(a0)), "r"(__float_as_uint(a1)),
          "r"(__float_as_uint(a2)), "r"(__float_as_uint(a3)),
          "r"(__float_as_uint(b0)), "r"(__float_as_uint(b1)));
}

// SMEM layout (floats):
//   [0,     20800)  xst: x[40][520]  (rows 0..511 used)   -> later Wlin (12288)
//   [20800, 40768)  Bs:  B[832][24]                       -> later basis[512][18]
//   [40768, 42432)  idxs: uint2[832]
#define XST_OFF 0
#define BS_OFF  20800
#define IDX_OFF 40768
#define SMEM_FLOATS 42432
#define SMEM_BYTES  (SMEM_FLOATS * 4)

__global__ __launch_bounds__(NT, 1)
void main_kernel(const float* __restrict__ f0,  const float* __restrict__ f1,
                 const float* __restrict__ f2,  const float* __restrict__ f3,
                 const float* __restrict__ attrs,
                 const float* __restrict__ W1_0, const float* __restrict__ W2_0,
                 const float* __restrict__ Wl0,  const float* __restrict__ sc0,
                 const float* __restrict__ W1_1, const float* __restrict__ W2_1,
                 const float* __restrict__ Wl1,  const float* __restrict__ sc1,
                 const float* __restrict__ W1_2, const float* __restrict__ W2_2,
                 const float* __restrict__ Wl2,  const float* __restrict__ sc2,
                 float* __restrict__ out, int B) {
    extern __shared__ float S[];
    float* xst = S + XST_OFF;
    float* BsS = S + BS_OFF;
    uint2* idxs = (uint2*)(S + IDX_OFF);
    float* bas = S + BS_OFF;      // reuse after mma
    float* wlS = S + XST_OFF;     // reuse after a1

    const int tid  = threadIdx.x;
    const int lane = tid & 31;
    const int wid  = tid >> 5;

    // ---- cooperative loads ----
    for (int t = tid; t < KP * 16; t += NT) {
        int k = t >> 4, n = t & 15;
        BsS[k * BST + n] = g_B[t];
    }
    for (int t = tid; t < KP; t += NT) idxs[t] = g_idx[t];

    // x gather: thread handles rows tid and tid+256
#pragma unroll
    for (int s = 0; s < 2; s++) {
        int row = tid + s * 256;
        int bb = blockIdx.x * NB + (row >> 6); if (bb >= B) bb = B - 1;
        const int base = bb * 64 + (row & 63);
        xst[0 * XST + row] = f0[base];
#pragma unroll
        for (int k = 0; k < 3; k++)  xst[(1 + k) * XST + row]  = f1[base * 3 + k];
#pragma unroll
        for (int k = 0; k < 9; k++)  xst[(4 + k) * XST + row]  = f2[base * 9 + k];
#pragma unroll
        for (int k = 0; k < 27; k++) xst[(13 + k) * XST + row] = f3[base * 27 + k];
    }
    __syncthreads();

    // ---- tensor phase: a2 = Y(x) @ U2fold via mma.sync tf32 ----
    // warp wid owns rows [wid*64, wid*64+64): 4 m16-tiles; N=16 (2 n8 tiles)
    const int q   = lane & 3;
    const int gid = lane >> 2;
    const int R0  = wid * 64;
    const char* xb = (const char*)xst;

    float cfr[4][2][4];
#pragma unroll
    for (int t = 0; t < 4; t++)
#pragma unroll
        for (int n = 0; n < 2; n++)
#pragma unroll
            for (int k = 0; k < 4; k++) cfr[t][n][k] = 0.0f;

    for (int ks = 0; ks < NSTEP; ks++) {
        const int k0 = ks * 8;
        uint2 o1 = idxs[k0 + q];
        uint2 o2 = idxs[k0 + q + 4];
        const int bi = (k0 + q) * BST + gid;
        float b00 = BsS[bi];
        float b10 = BsS[bi + 4 * BST];
        float b01 = BsS[bi + 8];
        float b11 = BsS[bi + 4 * BST + 8];
#pragma unroll
        for (int t = 0; t < 4; t++) {
            const int rb = (R0 + t * 16 + gid) * 4;
            float a0 = *(const float*)(xb + o1.x + rb)      * *(const float*)(xb + o1.y + rb);
            float a1v = *(const float*)(xb + o1.x + rb + 32) * *(const float*)(xb + o1.y + rb + 32);
            float a2v = *(const float*)(xb + o2.x + rb)      * *(const float*)(xb + o2.y + rb);
            float a3v = *(const float*)(xb + o2.x + rb + 32) * *(const float*)(xb + o2.y + rb + 32);
            mma_tf32(cfr[t][0], a0, a1v, a2v, a3v, b00, b10);
            mma_tf32(cfr[t][1], a0, a1v, a2v, a3v, b01, b11);
        }
    }
    __syncthreads();   // everyone done reading Bs before overwrite with basis

    // store C frags: bas[row][col], col = nt*8 + 2q (+1)
#pragma unroll
    for (int t = 0; t < 4; t++)
#pragma unroll
        for (int nt = 0; nt < 2; nt++) {
            const int row  = R0 + t * 16 + gid;
            const int colb = nt * 8 + 2 * q;
            *(float2*)&bas[row * BAS + colb]       = make_float2(cfr[t][nt][0], cfr[t][nt][1]);
            *(float2*)&bas[(row + 8) * BAS + colb] = make_float2(cfr[t][nt][2], cfr[t][nt][3]);
        }
    __syncthreads();

    // ---- a1 phase on CUDA cores (fp32, FFMA2 from constant) ----
    unsigned long long a1acc[2][7];
#pragma unroll
    for (int s = 0; s < 2; s++)
#pragma unroll
        for (int k = 0; k < 7; k++) a1acc[s][k] = 0ull;
    {
        const ulonglong2* trow = (const ulonglong2*)c_u1t;
#pragma unroll 4
        for (int i = 0; i < DIM; i++, trow += 4) {
            ulonglong2 q0 = trow[0];
            ulonglong2 q1 = trow[1];
            ulonglong2 q2 = trow[2];
            unsigned long long q3 = ((const unsigned long long*)trow)[6];
            unsigned long long y0 = dup2(xst[i * XST + tid]);
            unsigned long long y1 = dup2(xst[i * XST + tid + 256]);
            fma2(a1acc[0][0], q0.x, y0); fma2(a1acc[1][0], q0.x, y1);
            fma2(a1acc[0][1], q0.y, y0); fma2(a1acc[1][1], q0.y, y1);
            fma2(a1acc[0][2], q1.x, y0); fma2(a1acc[1][2], q1.x, y1);
            fma2(a1acc[0][3], q1.y, y0); fma2(a1acc[1][3], q1.y, y1);
            fma2(a1acc[0][4], q2.x, y0); fma2(a1acc[1][4], q2.x, y1);
            fma2(a1acc[0][5], q2.y, y0); fma2(a1acc[1][5], q2.y, y1);
            fma2(a1acc[0][6], q3,   y0); fma2(a1acc[1][6], q3,   y1);
        }
    }

    // ---- fold: basis = a1*w1 + a2*w2 (in place in bas) ----
    const int LSEL[14] = {0, 1, 1, 1, 2, 2, 2, 2, 2, 2, 2, 2, 2, 0};
#pragma unroll
    for (int s = 0; s < 2; s++) {
        const int row = tid + s * 256;
        int bb = blockIdx.x * NB + (row >> 6); if (bb >= B) bb = B - 1;
        const int cc = row & 63;
        float w10 = 0.f, w11 = 0.f, w12 = 0.f;
        float w20 = 0.f, w21 = 0.f, w22 = 0.f;
#pragma unroll
        for (int e = 0; e < 10; e++) {
            float a = __ldg(&attrs[bb * 10 + e]);
            w10 += a * __ldg(&W1_0[e * 64 + cc]);
            w20 += a * __ldg(&W2_0[e * 64 + cc]);
            w11 += a * __ldg(&W1_1[e * 64 + cc]);
            w21 += a * __ldg(&W2_1[e * 64 + cc]);
            w12 += a * __ldg(&W1_2[e * 64 + cc]);
            w22 += a * __ldg(&W2_2[e * 64 + cc]);
        }
        float w1v[3] = {w10, w11, w12};
        float w2v[3] = {w20, w21, w22};
        float* bp = bas + row * BAS;
#pragma unroll
        for (int k = 0; k < 7; k++) {
            float2 v1 = unpk2(a1acc[s][k]);
            int m0 = 2 * k, m1 = 2 * k + 1;
            bp[m0] = v1.x * w1v[LSEL[m0]] + bp[m0] * w2v[LSEL[m0]];
            if (m1 < 13)
                bp[m1] = v1.y * w1v[LSEL[m1]] + bp[m1] * w2v[LSEL[m1]];
        }
    }
    __syncthreads();

    // ---- Wlin cache into xst region (x no longer needed) ----
    {
        const float4* a0p = (const float4*)Wl0;
        const float4* a1p = (const float4*)Wl1;
        const float4* a2p = (const float4*)Wl2;
        float4* w4 = (float4*)wlS;
#pragma unroll
        for (int k = 0; k < 4; k++) {
            int idx = k * NT + tid;
            w4[idx]        = a0p[idx];
            w4[1024 + idx] = a1p[idx];
            w4[2048 + idx] = a2p[idx];
        }
    }
    __syncthreads();

    // ---- self-interaction: r[s][m] = sum_cc basis[b_s][cc][m] * Wlin_l[cc][c] ----
    const int g = tid >> 6;
    const int c = tid & 63;
    float r[2][13];
#pragma unroll
    for (int s = 0; s < 2; s++)
#pragma unroll
        for (int m = 0; m < 13; m++) r[s][m] = 0.0f;

#pragma unroll 2
    for (int cc = 0; cc < 64; cc++) {
        float wv0 = wlS[cc * 64 + c];
        float wv1 = wlS[4096 + cc * 64 + c];
        float wv2 = wlS[8192 + cc * 64 + c];
#pragma unroll
        for (int s = 0; s < 2; s++) {
            const float* br = bas + ((g * 2 + s) * 64 + cc) * BAS;
            float2 p0 = *(const float2*)(br);
            float2 p1 = *(const float2*)(br + 2);
            float2 p2 = *(const float2*)(br + 4);
            float2 p3 = *(const float2*)(br + 6);
            float2 p4 = *(const float2*)(br + 8);
            float2 p5 = *(const float2*)(br + 10);
            float  b12 = br[12];
            r[s][0]  += p0.x * wv0;
            r[s][1]  += p0.y * wv1;
            r[s][2]  += p1.x * wv1;
            r[s][3]  += p1.y * wv1;
            r[s][4]  += p2.x * wv2;
            r[s][5]  += p2.y * wv2;
            r[s][6]  += p3.x * wv2;
            r[s][7]  += p3.y * wv2;
            r[s][8]  += p4.x * wv2;
            r[s][9]  += p4.y * wv2;
            r[s][10] += p5.x * wv2;
            r[s][11] += p5.y * wv2;
            r[s][12] += b12  * wv2;
        }
    }

    // ---- outputs: concat [out0 (B,C)] [out1 (B,C,3)] [out2 (B,C,9)] ----
    float* o0 = out;
    float* o1 = out + (size_t)B * 64;
    float* o2 = out + (size_t)B * 64 * 4;
#pragma unroll
    for (int s = 0; s < 2; s++) {
        int bb = blockIdx.x * NB + g * 2 + s;
        if (bb >= B) break;
        const int bo = bb * 64 + c;
        o0[bo] = r[s][0] + __ldg(&sc0[bo]);
#pragma unroll
        for (int k = 0; k < 3; k++)
            o1[bo * 3 + k] = r[s][1 + k] + __ldg(&sc1[bo * 3 + k]);
#pragma unroll
        for (int k = 0; k < 9; k++)
            o2[bo * 9 + k] = r[s][4 + k] + __ldg(&sc2[bo * 9 + k]);
    }
}

extern "C" void kernel_launch(void* const* d_in, const int* in_sizes, int n_in,
                              void* d_out, int out_size) {
    const float* f0    = (const float*)d_in[0];
    const float* f1    = (const float*)d_in[1];
    const float* f2    = (const float*)d_in[2];
    const float* f3    = (const float*)d_in[3];
    const float* attrs = (const float*)d_in[4];
    const float* U2_0  = (const float*)d_in[5];
    const float* U1_0  = (const float*)d_in[6];
    const float* W1_0  = (const float*)d_in[7];
    const float* W2_0  = (const float*)d_in[8];
    const float* Wl0   = (const float*)d_in[9];
    const float* sc0   = (const float*)d_in[10];
    const float* U2_1  = (const float*)d_in[11];
    const float* U1_1  = (const float*)d_in[12];
    const float* W1_1  = (const float*)d_in[13];
    const float* W2_1  = (const float*)d_in[14];
    const float* Wl1   = (const float*)d_in[15];
    const float* sc1   = (const float*)d_in[16];
    const float* U2_2  = (const float*)d_in[17];
    const float* U1_2  = (const float*)d_in[18];
    const float* W1_2  = (const float*)d_in[19];
    const float* W2_2  = (const float*)d_in[20];
    const float* Wl2   = (const float*)d_in[21];
    const float* sc2   = (const float*)d_in[22];

    const int B = in_sizes[0] / 64;

    cudaFuncSetAttribute(main_kernel,
                         cudaFuncAttributeMaxDynamicSharedMemorySize, SMEM_BYTES);

    prep_kernel<<<(KP + DIM + 255) / 256, 256>>>(U2_0, U1_0, U2_1, U1_1, U2_2, U1_2);

    // copy staged U1 table into constant memory (graph-capturable D2D memcpy)
    void* src = nullptr;
    void* dst = nullptr;
    cudaGetSymbolAddress(&src, g_u1);
    cudaGetSymbolAddress(&dst, c_u1t);
    cudaMemcpyAsync(dst, src, DIM * 16 * sizeof(float),
                    cudaMemcpyDeviceToDevice, 0);

    const int grid = (B + NB - 1) / NB;
    main_kernel<<<grid, NT, SMEM_BYTES>>>(f0, f1, f2, f3, attrs,
                                          W1_0, W2_0, Wl0, sc0,
                                          W1_1, W2_1, Wl1, sc1,
                                          W1_2, W2_2, Wl2, sc2,
                                          (float*)d_out, B);
}

// round 16
// speedup vs baseline: 1.3318x; 1.0762x over previous
#include <cuda_runtime.h>
#include <stdint.h>

// ---- problem constants ----
#define NT     256
#define NB     8          // b per CTA
#define ROWS   512        // NB * 64 rows per CTA
#define DIM    40
#define NPAIR  820
#define KP2    960        // padded pairs: each i-run padded to multiple of 8
#define XST    520        // xst row stride (floats): 520%32=8 -> conflict-free xj loads
#define BST    24         // Bs row stride: q*24%32 = {0,24,16,8} -> conflict-free B frags
#define BAS    18         // basis row stride (floats)

// ---- staged tables (filled by prep_kernel) ----
// k-order: runs grouped by i (i outer), j consecutive from i, each run padded
// to a multiple of 8 rows with zero-coefficient rows.
__device__ float g_B[KP2 * 16];    // B[k][n]: tf32-rounded folded U2 coeffs
__device__ float g_u1[DIM * 16];   // U1 rows (13 coeffs + pad)
__constant__ float c_u1t[DIM * 16];

__global__ void prep_kernel(const float* __restrict__ U2_0,
                            const float* __restrict__ U1_0,
                            const float* __restrict__ U2_1,
                            const float* __restrict__ U1_1,
                            const float* __restrict__ U2_2,
                            const float* __restrict__ U1_2) {
    int idx = blockIdx.x * blockDim.x + threadIdx.x;
    if (idx >= KP2 + DIM) return;

    if (idx < KP2) {
        // locate (i, u) for padded-run layout: span(i) = ceil((40-i)/8)*8
        int i = 0, base = 0;
        for (;;) {
            int span = ((DIM - i + 7) >> 3) << 3;
            if (idx < base + span) break;
            base += span; i++;
        }
        int u = idx - base;              // position within padded run
        float row[16];
#pragma unroll
        for (int k = 0; k < 16; k++) row[k] = 0.0f;
        if (u < DIM - i) {               // real pair (i, j)
            int j = i + u;
            const float* U2b[3] = {U2_0, U2_1, U2_2};
#pragma unroll
            for (int m = 0; m < 13; m++) {
                int l  = (m == 0) ? 0 : ((m < 4) ? 1 : 2);
                int mm = (m == 0) ? 0 : ((m < 4) ? (m - 1) : (m - 4));
                const float* U = U2b[l];
                float v = U[(mm * DIM + i) * DIM + j];
                if (i != j) v += U[(mm * DIM + j) * DIM + i];
                unsigned int o;
                asm("cvt.rna.tf32.f32 %0, %1;" : "=r"(o) : "f"(v));
                row[m] = __uint_as_float(o);
            }
        }
#pragma unroll
        for (int k = 0; k < 16; k++) g_B[idx * 16 + k] = row[k];
    } else {
        int i = idx - KP2;
        float row[16];
#pragma unroll
        for (int k = 0; k < 16; k++) row[k] = 0.0f;
        const float* U1b[3] = {U1_0, U1_1, U1_2};
#pragma unroll
        for (int m = 0; m < 13; m++) {
            int l  = (m == 0) ? 0 : ((m < 4) ? 1 : 2);
            int mm = (m == 0) ? 0 : ((m < 4) ? (m - 1) : (m - 4));
            row[m] = U1b[l][mm * DIM + i];
        }
#pragma unroll
        for (int k = 0; k < 16; k++) g_u1[i * 16 + k] = row[k];
    }
}

// ---- packed f32x2 helpers (for the a1 phase) ----
__device__ __forceinline__ void fma2(unsigned long long& acc,
                                     unsigned long long u,
                                     unsigned long long y) {
    asm("fma.rn.f32x2 %0, %1, %2, %0;" : "+l"(acc) : "l"(u), "l"(y));
}
__device__ __forceinline__ unsigned long long dup2(float y) {
    unsigned long long r;
    asm("mov.b64 %0, {%1, %1};" : "=l"(r) : "f"(y));
    return r;
}
__device__ __forceinline__ float2 unpk2(unsigned long long v) {
    float2 r;
    asm("mov.b64 {%0, %1}, %2;" : "=f"(r.x), "=f"(r.y) : "l"(v));
    return r;
}

// ---- tf32 mma.sync m16n8k8 ----
__device__ __forceinline__ void mma_tf32(float* c,
                                         float a0, float a1, float a2, float a3,
                                         float b0, float b1) {
    asm volatile(
        "mma.sync.aligned.m16n8k8.row.col.f32.tf32.tf32.f32 "
        "{%0,%1,%2,%3},{%4,%5,%6,%7},{%8,%9},{%0,%1,%2,%3};"
        : "+f"(c[0]), "+f"(c[1]), "+f"(c[2]), "+f"(c[3])
        : "r"(__float_as_uint(a0)), "r"(__float_as_uint(a1)),
          "r"(__float_as_uint(a2)), "r"(__float_as_uint(a3)),
          "r"(__float_as_uint(b0)), "r"(__float_as_uint(b1)));
}

// SMEM layout (floats):
//   [0,     20800)  xst: x[40][520]  (rows 0..511 used)   -> later Wlin (12288)
//   [20800, 43840)  Bs:  B[960][24]                       -> later basis[512][18]
#define XST_OFF 0
#define BS_OFF  20800
#define SMEM_FLOATS 43840
#define SMEM_BYTES  (SMEM_FLOATS * 4)

__global__ __launch_bounds__(NT, 1)
void main_kernel(const float* __restrict__ f0,  const float* __restrict__ f1,
                 const float* __restrict__ f2,  const float* __restrict__ f3,
                 const float* __restrict__ attrs,
                 const float* __restrict__ W1_0, const float* __restrict__ W2_0,
                 const float* __restrict__ Wl0,  const float* __restrict__ sc0,
                 const float* __restrict__ W1_1, const float* __restrict__ W2_1,
                 const float* __restrict__ Wl1,  const float* __restrict__ sc1,
                 const float* __restrict__ W1_2, const float* __restrict__ W2_2,
                 const float* __restrict__ Wl2,  const float* __restrict__ sc2,
                 float* __restrict__ out, int B) {
    extern __shared__ float S[];
    float* xst = S + XST_OFF;
    float* BsS = S + BS_OFF;
    float* bas = S + BS_OFF;      // reuse after mma
    float* wlS = S + XST_OFF;     // reuse after a1

    const int tid  = threadIdx.x;
    const int lane = tid & 31;
    const int wid  = tid >> 5;

    // ---- cooperative loads ----
    for (int t = tid; t < KP2 * 16; t += NT) {
        int k = t >> 4, n = t & 15;
        BsS[k * BST + n] = g_B[t];
    }

    // x gather: thread handles rows tid and tid+256
#pragma unroll
    for (int s = 0; s < 2; s++) {
        int row = tid + s * 256;
        int bb = blockIdx.x * NB + (row >> 6); if (bb >= B) bb = B - 1;
        const int base = bb * 64 + (row & 63);
        xst[0 * XST + row] = f0[base];
#pragma unroll
        for (int k = 0; k < 3; k++)  xst[(1 + k) * XST + row]  = f1[base * 3 + k];
#pragma unroll
        for (int k = 0; k < 9; k++)  xst[(4 + k) * XST + row]  = f2[base * 9 + k];
#pragma unroll
        for (int k = 0; k < 27; k++) xst[(13 + k) * XST + row] = f3[base * 27 + k];
    }
    __syncthreads();

    // ---- tensor phase: a2 = Y(x) @ U2fold via mma.sync tf32 ----
    // k-order grouped by i: xi hoisted per i-run, j computable (no idx table).
    const int q   = lane & 3;
    const int gid = lane >> 2;
    const int R0  = wid * 64;

    float cfr[4][2][4];
#pragma unroll
    for (int t = 0; t < 4; t++)
#pragma unroll
        for (int n = 0; n < 2; n++)
#pragma unroll
            for (int k = 0; k < 4; k++) cfr[t][n][k] = 0.0f;

    {
        const float* Bp = BsS;
        for (int i = 0; i < DIM; i++) {
            // hoist xi per row-tile (same i for the whole run)
            float xi0[4], xi1[4];
#pragma unroll
            for (int t = 0; t < 4; t++) {
                int r = R0 + t * 16 + gid;
                xi0[t] = xst[i * XST + r];
                xi1[t] = xst[i * XST + r + 8];
            }
            const int nks = (DIM - i + 7) >> 3;
            int jb = i;
            for (int s = 0; s < nks; s++) {
                int j1 = jb + q;     if (j1 > DIM - 1) j1 = DIM - 1;
                int j2 = jb + q + 4; if (j2 > DIM - 1) j2 = DIM - 1;
                const float* xj1 = xst + j1 * XST;
                const float* xj2 = xst + j2 * XST;
                float b00 = Bp[q * BST + gid];
                float b10 = Bp[(q + 4) * BST + gid];
                float b01 = Bp[q * BST + gid + 8];
                float b11 = Bp[(q + 4) * BST + gid + 8];
#pragma unroll
                for (int t = 0; t < 4; t++) {
                    const int r = R0 + t * 16 + gid;
                    float a0  = xi0[t] * xj1[r];
                    float a1v = xi1[t] * xj1[r + 8];
                    float a2v = xi0[t] * xj2[r];
                    float a3v = xi1[t] * xj2[r + 8];
                    mma_tf32(cfr[t][0], a0, a1v, a2v, a3v, b00, b10);
                    mma_tf32(cfr[t][1], a0, a1v, a2v, a3v, b01, b11);
                }
                Bp += 8 * BST;
                jb += 8;
            }
        }
    }
    __syncthreads();   // everyone done reading Bs before overwrite with basis

    // store C frags: bas[row][col], col = nt*8 + 2q (+1)
#pragma unroll
    for (int t = 0; t < 4; t++)
#pragma unroll
        for (int nt = 0; nt < 2; nt++) {
            const int row  = R0 + t * 16 + gid;
            const int colb = nt * 8 + 2 * q;
            *(float2*)&bas[row * BAS + colb]       = make_float2(cfr[t][nt][0], cfr[t][nt][1]);
            *(float2*)&bas[(row + 8) * BAS + colb] = make_float2(cfr[t][nt][2], cfr[t][nt][3]);
        }
    __syncthreads();

    // ---- a1 phase on CUDA cores (fp32, FFMA2 from constant) ----
    unsigned long long a1acc[2][7];
#pragma unroll
    for (int s = 0; s < 2; s++)
#pragma unroll
        for (int k = 0; k < 7; k++) a1acc[s][k] = 0ull;
    {
        const ulonglong2* trow = (const ulonglong2*)c_u1t;
#pragma unroll 4
        for (int i = 0; i < DIM; i++, trow += 4) {
            ulonglong2 q0 = trow[0];
            ulonglong2 q1 = trow[1];
            ulonglong2 q2 = trow[2];
            unsigned long long q3 = ((const unsigned long long*)trow)[6];
            unsigned long long y0 = dup2(xst[i * XST + tid]);
            unsigned long long y1 = dup2(xst[i * XST + tid + 256]);
            fma2(a1acc[0][0], q0.x, y0); fma2(a1acc[1][0], q0.x, y1);
            fma2(a1acc[0][1], q0.y, y0); fma2(a1acc[1][1], q0.y, y1);
            fma2(a1acc[0][2], q1.x, y0); fma2(a1acc[1][2], q1.x, y1);
            fma2(a1acc[0][3], q1.y, y0); fma2(a1acc[1][3], q1.y, y1);
            fma2(a1acc[0][4], q2.x, y0); fma2(a1acc[1][4], q2.x, y1);
            fma2(a1acc[0][5], q2.y, y0); fma2(a1acc[1][5], q2.y, y1);
            fma2(a1acc[0][6], q3,   y0); fma2(a1acc[1][6], q3,   y1);
        }
    }

    // ---- fold: basis = a1*w1 + a2*w2 (in place in bas) ----
    const int LSEL[14] = {0, 1, 1, 1, 2, 2, 2, 2, 2, 2, 2, 2, 2, 0};
#pragma unroll
    for (int s = 0; s < 2; s++) {
        const int row = tid + s * 256;
        int bb = blockIdx.x * NB + (row >> 6); if (bb >= B) bb = B - 1;
        const int cc = row & 63;
        float w10 = 0.f, w11 = 0.f, w12 = 0.f;
        float w20 = 0.f, w21 = 0.f, w22 = 0.f;
#pragma unroll
        for (int e = 0; e < 10; e++) {
            float a = __ldg(&attrs[bb * 10 + e]);
            w10 += a * __ldg(&W1_0[e * 64 + cc]);
            w20 += a * __ldg(&W2_0[e * 64 + cc]);
            w11 += a * __ldg(&W1_1[e * 64 + cc]);
            w21 += a * __ldg(&W2_1[e * 64 + cc]);
            w12 += a * __ldg(&W1_2[e * 64 + cc]);
            w22 += a * __ldg(&W2_2[e * 64 + cc]);
        }
        float w1v[3] = {w10, w11, w12};
        float w2v[3] = {w20, w21, w22};
        float* bp = bas + row * BAS;
#pragma unroll
        for (int k = 0; k < 7; k++) {
            float2 v1 = unpk2(a1acc[s][k]);
            int m0 = 2 * k, m1 = 2 * k + 1;
            bp[m0] = v1.x * w1v[LSEL[m0]] + bp[m0] * w2v[LSEL[m0]];
            if (m1 < 13)
                bp[m1] = v1.y * w1v[LSEL[m1]] + bp[m1] * w2v[LSEL[m1]];
        }
    }
    __syncthreads();

    // ---- Wlin cache into xst region (x no longer needed) ----
    {
        const float4* a0p = (const float4*)Wl0;
        const float4* a1p = (const float4*)Wl1;
        const float4* a2p = (const float4*)Wl2;
        float4* w4 = (float4*)wlS;
#pragma unroll
        for (int k = 0; k < 4; k++) {
            int idx = k * NT + tid;
            w4[idx]        = a0p[idx];
            w4[1024 + idx] = a1p[idx];
            w4[2048 + idx] = a2p[idx];
        }
    }
    __syncthreads();

    // ---- self-interaction: r[s][m] = sum_cc basis[b_s][cc][m] * Wlin_l[cc][c] ----
    const int g = tid >> 6;
    const int c = tid & 63;
    float r[2][13];
#pragma unroll
    for (int s = 0; s < 2; s++)
#pragma unroll
        for (int m = 0; m < 13; m++) r[s][m] = 0.0f;

#pragma unroll 2
    for (int cc = 0; cc < 64; cc++) {
        float wv0 = wlS[cc * 64 + c];
        float wv1 = wlS[4096 + cc * 64 + c];
        float wv2 = wlS[8192 + cc * 64 + c];
#pragma unroll
        for (int s = 0; s < 2; s++) {
            const float* br = bas + ((g * 2 + s) * 64 + cc) * BAS;
            float2 p0 = *(const float2*)(br);
            float2 p1 = *(const float2*)(br + 2);
            float2 p2 = *(const float2*)(br + 4);
            float2 p3 = *(const float2*)(br + 6);
            float2 p4 = *(const float2*)(br + 8);
            float2 p5 = *(const float2*)(br + 10);
            float  b12 = br[12];
            r[s][0]  += p0.x * wv0;
            r[s][1]  += p0.y * wv1;
            r[s][2]  += p1.x * wv1;
            r[s][3]  += p1.y * wv1;
            r[s][4]  += p2.x * wv2;
            r[s][5]  += p2.y * wv2;
            r[s][6]  += p3.x * wv2;
            r[s][7]  += p3.y * wv2;
            r[s][8]  += p4.x * wv2;
            r[s][9]  += p4.y * wv2;
            r[s][10] += p5.x * wv2;
            r[s][11] += p5.y * wv2;
            r[s][12] += b12  * wv2;
        }
    }

    // ---- outputs: concat [out0 (B,C)] [out1 (B,C,3)] [out2 (B,C,9)] ----
    float* o0 = out;
    float* o1 = out + (size_t)B * 64;
    float* o2 = out + (size_t)B * 64 * 4;
#pragma unroll
    for (int s = 0; s < 2; s++) {
        int bb = blockIdx.x * NB + g * 2 + s;
        if (bb >= B) break;
        const int bo = bb * 64 + c;
        o0[bo] = r[s][0] + __ldg(&sc0[bo]);
#pragma unroll
        for (int k = 0; k < 3; k++)
            o1[bo * 3 + k] = r[s][1 + k] + __ldg(&sc1[bo * 3 + k]);
#pragma unroll
        for (int k = 0; k < 9; k++)
            o2[bo * 9 + k] = r[s][4 + k] + __ldg(&sc2[bo * 9 + k]);
    }
}

extern "C" void kernel_launch(void* const* d_in, const int* in_sizes, int n_in,
                              void* d_out, int out_size) {
    const float* f0    = (const float*)d_in[0];
    const float* f1    = (const float*)d_in[1];
    const float* f2    = (const float*)d_in[2];
    const float* f3    = (const float*)d_in[3];
    const float* attrs = (const float*)d_in[4];
    const float* U2_0  = (const float*)d_in[5];
    const float* U1_0  = (const float*)d_in[6];
    const float* W1_0  = (const float*)d_in[7];
    const float* W2_0  = (const float*)d_in[8];
    const float* Wl0   = (const float*)d_in[9];
    const float* sc0   = (const float*)d_in[10];
    const float* U2_1  = (const float*)d_in[11];
    const float* U1_1  = (const float*)d_in[12];
    const float* W1_1  = (const float*)d_in[13];
    const float* W2_1  = (const float*)d_in[14];
    const float* Wl1   = (const float*)d_in[15];
    const float* sc1   = (const float*)d_in[16];
    const float* U2_2  = (const float*)d_in[17];
    const float* U1_2  = (const float*)d_in[18];
    const float* W1_2  = (const float*)d_in[19];
    const float* W2_2  = (const float*)d_in[20];
    const float* Wl2   = (const float*)d_in[21];
    const float* sc2   = (const float*)d_in[22];

    const int B = in_sizes[0] / 64;

    cudaFuncSetAttribute(main_kernel,
                         cudaFuncAttributeMaxDynamicSharedMemorySize, SMEM_BYTES);

    prep_kernel<<<(KP2 + DIM + 255) / 256, 256>>>(U2_0, U1_0, U2_1, U1_1, U2_2, U1_2);

    // copy staged U1 table into constant memory (graph-capturable D2D memcpy)
    void* src = nullptr;
    void* dst = nullptr;
    cudaGetSymbolAddress(&src, g_u1);
    cudaGetSymbolAddress(&dst, c_u1t);
    cudaMemcpyAsync(dst, src, DIM * 16 * sizeof(float),
                    cudaMemcpyDeviceToDevice, 0);

    const int grid = (B + NB - 1) / NB;
    main_kernel<<<grid, NT, SMEM_BYTES>>>(f0, f1, f2, f3, attrs,
                                          W1_0, W2_0, Wl0, sc0,
                                          W1_1, W2_1, Wl1, sc1,
                                          W1_2, W2_2, Wl2, sc2,
                                          (float*)d_out, B);
}